// round 4
// baseline (speedup 1.0000x reference)
#include <cuda_runtime.h>
#include <cuda_bf16.h>
#include <cstdint>
#include <math.h>

#define B_ 1024
#define D_ 512
#define K_ 256
#define J_ 1024   // reduction length: [x^2 | x]

// ---------------- scratch (no allocations allowed) ----------------
__device__ __nv_bfloat16 g_Ahi[B_ * J_];
__device__ __nv_bfloat16 g_Alo[B_ * J_];
__device__ __nv_bfloat16 g_Bhi[K_ * J_];
__device__ __nv_bfloat16 g_Blo[K_ * J_];
__device__ float g_C[K_];

__device__ __forceinline__ uint32_t smem_u32(const void* p) {
    uint32_t a;
    asm("{ .reg .u64 t; cvta.to.shared.u64 t, %1; cvt.u32.u64 %0, t; }" : "=r"(a) : "l"(p));
    return a;
}
__device__ __forceinline__ void cpasync16(uint32_t dst, const void* src) {
    asm volatile("cp.async.cg.shared.global [%0], [%1], 16;\n" :: "r"(dst), "l"(src) : "memory");
}

// ---------------------------------------------------------------------------
// Fused prep.
//  blocks [0, 512): U rows from x (bf16 hi/lo split).
//  blocks [512, 544): V rows (one warp per k) + warp-shfl C reduction.
//  blocks [544, 608): zero-init out (gemm accumulates into it atomically).
// ---------------------------------------------------------------------------
#define NB_U 512
#define NB_V 32
#define NB_Z 64

__global__ __launch_bounds__(256) void prep_kernel(const float* __restrict__ x,
                                                   const float* __restrict__ means,
                                                   const float* __restrict__ rho,
                                                   float* __restrict__ out) {
    const int blk = blockIdx.x;
    const int tid = threadIdx.x;
    if (blk < NB_U) {
        const int idx = blk * 256 + tid;           // float4 index over B*D/4
        const int b = idx >> 7;                    // 128 float4 per row of x
        const int d = (idx & 127) * 4;
        float4 xv = ((const float4*)x)[idx];
        float vsq[4] = {xv.x * xv.x, xv.y * xv.y, xv.z * xv.z, xv.w * xv.w};
        float vx[4]  = {xv.x, xv.y, xv.z, xv.w};
        __nv_bfloat16 hsq[4], lsq[4], hx[4], lx[4];
        #pragma unroll
        for (int i = 0; i < 4; i++) {
            hsq[i] = __float2bfloat16(vsq[i]);
            lsq[i] = __float2bfloat16(vsq[i] - __bfloat162float(hsq[i]));
            hx[i]  = __float2bfloat16(vx[i]);
            lx[i]  = __float2bfloat16(vx[i] - __bfloat162float(hx[i]));
        }
        size_t base = (size_t)b * J_ + d;
        *(__nv_bfloat162*)&g_Ahi[base]          = __halves2bfloat162(hsq[0], hsq[1]);
        *(__nv_bfloat162*)&g_Ahi[base + 2]      = __halves2bfloat162(hsq[2], hsq[3]);
        *(__nv_bfloat162*)&g_Alo[base]          = __halves2bfloat162(lsq[0], lsq[1]);
        *(__nv_bfloat162*)&g_Alo[base + 2]      = __halves2bfloat162(lsq[2], lsq[3]);
        *(__nv_bfloat162*)&g_Ahi[base + D_]     = __halves2bfloat162(hx[0], hx[1]);
        *(__nv_bfloat162*)&g_Ahi[base + D_ + 2] = __halves2bfloat162(hx[2], hx[3]);
        *(__nv_bfloat162*)&g_Alo[base + D_]     = __halves2bfloat162(lx[0], lx[1]);
        *(__nv_bfloat162*)&g_Alo[base + D_ + 2] = __halves2bfloat162(lx[2], lx[3]);
    } else if (blk < NB_U + NB_V) {
        const int wid = tid >> 5, lane = tid & 31;
        const int k = (blk - NB_U) * 8 + wid;      // 32 blocks x 8 warps = 256 k's
        const float4* mrow = (const float4*)(means + (size_t)k * D_);
        const float4* rrow = (const float4*)(rho   + (size_t)k * D_);
        float csum = 0.0f;
        #pragma unroll
        for (int i = 0; i < 4; i++) {
            int d4 = lane + i * 32;                // float4 index 0..127
            float4 m = mrow[d4];
            float4 r = rrow[d4];
            float mm[4] = {m.x, m.y, m.z, m.w};
            float rr[4] = {r.x, r.y, r.z, r.w};
            __nv_bfloat16 h0[4], l0[4], h1[4], l1[4];
            #pragma unroll
            for (int c = 0; c < 4; c++) {
                float s  = __logf(1.0f + __expf(rr[c]));   // softplus (fast)
                float s2 = s * s;
                float v0 = 0.5f * s2;
                float v1 = -mm[c] * s2;
                h0[c] = __float2bfloat16(v0);
                l0[c] = __float2bfloat16(v0 - __bfloat162float(h0[c]));
                h1[c] = __float2bfloat16(v1);
                l1[c] = __float2bfloat16(v1 - __bfloat162float(h1[c]));
                csum += 0.5f * mm[c] * mm[c] * s2;
            }
            size_t base = (size_t)k * J_ + d4 * 4;
            *(__nv_bfloat162*)&g_Bhi[base]          = __halves2bfloat162(h0[0], h0[1]);
            *(__nv_bfloat162*)&g_Bhi[base + 2]      = __halves2bfloat162(h0[2], h0[3]);
            *(__nv_bfloat162*)&g_Blo[base]          = __halves2bfloat162(l0[0], l0[1]);
            *(__nv_bfloat162*)&g_Blo[base + 2]      = __halves2bfloat162(l0[2], l0[3]);
            *(__nv_bfloat162*)&g_Bhi[base + D_]     = __halves2bfloat162(h1[0], h1[1]);
            *(__nv_bfloat162*)&g_Bhi[base + D_ + 2] = __halves2bfloat162(h1[2], h1[3]);
            *(__nv_bfloat162*)&g_Blo[base + D_]     = __halves2bfloat162(l1[0], l1[1]);
            *(__nv_bfloat162*)&g_Blo[base + D_ + 2] = __halves2bfloat162(l1[2], l1[3]);
        }
        #pragma unroll
        for (int off = 16; off > 0; off >>= 1)
            csum += __shfl_xor_sync(0xFFFFFFFFu, csum, off);
        if (lane == 0) g_C[k] = csum;
    } else {
        // zero-init out: 64 blocks x 256 threads x 4 float4 = 65536 float4 = 1MB
        float4* o4 = (float4*)out;
        const int base = (blk - NB_U - NB_V) * 1024 + tid;
        const float4 z = make_float4(0.f, 0.f, 0.f, 0.f);
        #pragma unroll
        for (int i = 0; i < 4; i++) o4[base + i * 256] = z;
    }
}

// ---------------------------------------------------------------------------
// HMMA GEMM with split-K=2: out[1024,256] += U*V^T (+ C via 0.5*C per split).
// CTA tile 64x32, KC=64 per stage, double-buffered, 2 CTAs/SM resident.
// Grid (16, 8, 2) = 256 CTAs, all resident in one wave.
// ---------------------------------------------------------------------------
#define BM 64
#define BN 32
#define KC 64
#define KSPLIT 2
#define KPER (J_ / KSPLIT)        // 512
#define NSTAGE (KPER / KC)        // 8
#define ROWB 144                  // 64 bf16 (128B) + 16B pad -> conflict-free ldmatrix
#define OFF_AH 0
#define OFF_AL (BM * ROWB)                    // 9216
#define OFF_BH (2 * BM * ROWB)                // 18432
#define OFF_BL (2 * BM * ROWB + BN * ROWB)    // 23040
#define STAGE_BYTES (2 * BM * ROWB + 2 * BN * ROWB)   // 27648

__device__ __forceinline__ void ldm4(uint32_t* f, uint32_t addr) {
    asm volatile("ldmatrix.sync.aligned.m8n8.x4.shared.b16 {%0,%1,%2,%3}, [%4];"
                 : "=r"(f[0]), "=r"(f[1]), "=r"(f[2]), "=r"(f[3]) : "r"(addr));
}
__device__ __forceinline__ void mma16816(float* c, const uint32_t* a, uint32_t b0, uint32_t b1) {
    asm volatile("mma.sync.aligned.m16n8k16.row.col.f32.bf16.bf16.f32 "
                 "{%0,%1,%2,%3}, {%4,%5,%6,%7}, {%8,%9}, {%0,%1,%2,%3};"
                 : "+f"(c[0]), "+f"(c[1]), "+f"(c[2]), "+f"(c[3])
                 : "r"(a[0]), "r"(a[1]), "r"(a[2]), "r"(a[3]), "r"(b0), "r"(b1));
}

__device__ __forceinline__ void load_stage(uint32_t sb, int m0, int n0, int kelem, int tid) {
    const char* baseAh = (const char*)g_Ahi;
    const char* baseAl = (const char*)g_Alo;
    const char* baseBh = (const char*)g_Bhi;
    const char* baseBl = (const char*)g_Blo;
    const size_t kb = (size_t)kelem * 2;   // byte offset within a 2048B row
    #pragma unroll
    for (int i = 0; i < 2; i++) {          // A: 64 rows x 8 chunks = 512 positions
        int idx = tid + i * 256;
        int r = idx >> 3, c = idx & 7;
        uint32_t so = (uint32_t)(r * ROWB + c * 16);
        size_t go = (size_t)(m0 + r) * 2048 + kb + c * 16;
        cpasync16(sb + OFF_AH + so, baseAh + go);
        cpasync16(sb + OFF_AL + so, baseAl + go);
    }
    {                                      // B: 32 rows x 8 chunks = 256 positions
        int r = tid >> 3, c = tid & 7;
        uint32_t so = (uint32_t)(r * ROWB + c * 16);
        size_t go = (size_t)(n0 + r) * 2048 + kb + c * 16;
        cpasync16(sb + OFF_BH + so, baseBh + go);
        cpasync16(sb + OFF_BL + so, baseBl + go);
    }
    asm volatile("cp.async.commit_group;\n" ::: "memory");
}

__global__ __launch_bounds__(256, 2) void gemm_kernel(float* __restrict__ out) {
    extern __shared__ char dyn[];
    __shared__ float Cs[BN];

    const int tid = threadIdx.x;
    const int wid = tid >> 5, lane = tid & 31;
    const int m0 = blockIdx.x * BM;
    const int n0 = blockIdx.y * BN;
    const int kbase = blockIdx.z * KPER;
    const int mw = (wid & 3) * 16;         // warp M offset
    const int nw = (wid >> 2) * 16;        // warp N offset

    const uint32_t sbase = smem_u32(dyn);

    load_stage(sbase, m0, n0, kbase, tid);
    if (tid < BN) Cs[tid] = g_C[n0 + tid];

    float acc0[4] = {0.f, 0.f, 0.f, 0.f};  // cols nw..nw+7
    float acc1[4] = {0.f, 0.f, 0.f, 0.f};  // cols nw+8..nw+15

    const uint32_t aRow = (uint32_t)((mw + (lane & 15)) * ROWB);
    const uint32_t aCol = (uint32_t)((lane >> 4) * 16);
    const uint32_t bRow = (uint32_t)((nw + (lane & 7) + ((lane >> 4) << 3)) * ROWB);
    const uint32_t bCol = (uint32_t)((((lane >> 3) & 1) << 3) * 2);

    for (int s = 0; s < NSTAGE; s++) {
        if (s + 1 < NSTAGE) {
            load_stage(sbase + ((s + 1) & 1) * STAGE_BYTES, m0, n0, kbase + (s + 1) * KC, tid);
            asm volatile("cp.async.wait_group 1;\n" ::: "memory");
        } else {
            asm volatile("cp.async.wait_group 0;\n" ::: "memory");
        }
        __syncthreads();

        const uint32_t sb = sbase + (s & 1) * STAGE_BYTES;
        #pragma unroll
        for (int kk = 0; kk < KC / 16; kk++) {
            const uint32_t kb = (uint32_t)(kk * 32);
            uint32_t aH[4], aL[4], bH[4], bL[4];
            ldm4(aH, sb + OFF_AH + aRow + aCol + kb);
            ldm4(aL, sb + OFF_AL + aRow + aCol + kb);
            ldm4(bH, sb + OFF_BH + bRow + bCol + kb);
            ldm4(bL, sb + OFF_BL + bRow + bCol + kb);
            mma16816(acc0, aH, bH[0], bH[1]);
            mma16816(acc1, aH, bH[2], bH[3]);
            mma16816(acc0, aH, bL[0], bL[1]);
            mma16816(acc1, aH, bL[2], bL[3]);
            mma16816(acc0, aL, bH[0], bH[1]);
            mma16816(acc1, aL, bH[2], bH[3]);
        }
        __syncthreads();
    }

    // Epilogue: atomic accumulate into out (zero-initialized by prep).
    // Each split contributes 0.5*C so the two splits together add C exactly once.
    const int row = lane >> 2;
    const int col = (lane & 3) * 2;
    const int gr0 = m0 + mw + row;
    const int gc0 = n0 + nw + col;
    const float c00 = 0.5f * Cs[nw + col],     c01 = 0.5f * Cs[nw + col + 1];
    const float c10 = 0.5f * Cs[nw + col + 8], c11 = 0.5f * Cs[nw + col + 9];
    float* o0 = out + (size_t)gr0 * K_ + gc0;
    float* o1 = out + (size_t)(gr0 + 8) * K_ + gc0;
    atomicAdd(o0 + 0, acc0[0] + c00);
    atomicAdd(o0 + 1, acc0[1] + c01);
    atomicAdd(o1 + 0, acc0[2] + c00);
    atomicAdd(o1 + 1, acc0[3] + c01);
    atomicAdd(o0 + 8, acc1[0] + c10);
    atomicAdd(o0 + 9, acc1[1] + c11);
    atomicAdd(o1 + 8, acc1[2] + c10);
    atomicAdd(o1 + 9, acc1[3] + c11);
}

// ---------------------------------------------------------------------------
extern "C" void kernel_launch(void* const* d_in, const int* in_sizes, int n_in,
                              void* d_out, int out_size) {
    const float* x     = (const float*)d_in[0];
    const float* means = (const float*)d_in[1];
    const float* rho   = (const float*)d_in[2];
    float* out = (float*)d_out;

    cudaFuncSetAttribute(gemm_kernel, cudaFuncAttributeMaxDynamicSharedMemorySize,
                         2 * STAGE_BYTES);

    prep_kernel<<<NB_U + NB_V + NB_Z, 256>>>(x, means, rho, out);
    gemm_kernel<<<dim3(B_ / BM, K_ / BN, KSPLIT), 256, 2 * STAGE_BYTES>>>(out);
}

// round 5
// speedup vs baseline: 1.3170x; 1.3170x over previous
#include <cuda_runtime.h>
#include <cuda_fp16.h>
#include <cstdint>
#include <math.h>

#define B_ 1024
#define D_ 512
#define K_ 256
#define J_ 1024   // reduction length: [x^2 | x]

// ---------------- scratch (no allocations allowed) ----------------
__device__ __half g_A[B_ * J_];   // [b][j]: j<512 -> x^2, j>=512 -> x
__device__ __half g_Bv[K_ * J_];  // [k][j]: j<512 -> 0.5*s2, j>=512 -> -m*s2
__device__ float g_C[K_];         // 0.5 * sum_d m^2 s2

__device__ __forceinline__ uint32_t smem_u32(const void* p) {
    uint32_t a;
    asm("{ .reg .u64 t; cvta.to.shared.u64 t, %1; cvt.u32.u64 %0, t; }" : "=r"(a) : "l"(p));
    return a;
}
__device__ __forceinline__ void cpasync16(uint32_t dst, const void* src) {
    asm volatile("cp.async.cg.shared.global [%0], [%1], 16;\n" :: "r"(dst), "l"(src) : "memory");
}

// ---------------------------------------------------------------------------
// Fused prep.
//  blocks [0, 512): U rows from x (fp16).
//  blocks [512, 544): V rows (one warp per k) + warp-shfl C reduction.
//  blocks [544, 608): zero-init out (gemm accumulates atomically).
// ---------------------------------------------------------------------------
#define NB_U 512
#define NB_V 32
#define NB_Z 64

__global__ __launch_bounds__(256) void prep_kernel(const float* __restrict__ x,
                                                   const float* __restrict__ means,
                                                   const float* __restrict__ rho,
                                                   float* __restrict__ out) {
    const int blk = blockIdx.x;
    const int tid = threadIdx.x;
    if (blk < NB_U) {
        const int idx = blk * 256 + tid;           // float4 index over B*D/4
        const int b = idx >> 7;                    // 128 float4 per row of x
        const int d = (idx & 127) * 4;
        float4 xv = ((const float4*)x)[idx];
        size_t base = (size_t)b * J_ + d;
        *(__half2*)&g_A[base]          = __floats2half2_rn(xv.x * xv.x, xv.y * xv.y);
        *(__half2*)&g_A[base + 2]      = __floats2half2_rn(xv.z * xv.z, xv.w * xv.w);
        *(__half2*)&g_A[base + D_]     = __floats2half2_rn(xv.x, xv.y);
        *(__half2*)&g_A[base + D_ + 2] = __floats2half2_rn(xv.z, xv.w);
    } else if (blk < NB_U + NB_V) {
        const int wid = tid >> 5, lane = tid & 31;
        const int k = (blk - NB_U) * 8 + wid;      // 32 blocks x 8 warps = 256 k's
        const float4* mrow = (const float4*)(means + (size_t)k * D_);
        const float4* rrow = (const float4*)(rho   + (size_t)k * D_);
        float csum = 0.0f;
        #pragma unroll
        for (int i = 0; i < 4; i++) {
            int d4 = lane + i * 32;                // float4 index 0..127
            float4 m = mrow[d4];
            float4 r = rrow[d4];
            float mm[4] = {m.x, m.y, m.z, m.w};
            float rr[4] = {r.x, r.y, r.z, r.w};
            float v0[4], v1[4];
            #pragma unroll
            for (int c = 0; c < 4; c++) {
                float s  = __logf(1.0f + __expf(rr[c]));   // softplus (fast)
                float s2 = s * s;
                v0[c] = 0.5f * s2;
                v1[c] = -mm[c] * s2;
                csum += 0.5f * mm[c] * mm[c] * s2;
            }
            size_t base = (size_t)k * J_ + d4 * 4;
            *(__half2*)&g_Bv[base]          = __floats2half2_rn(v0[0], v0[1]);
            *(__half2*)&g_Bv[base + 2]      = __floats2half2_rn(v0[2], v0[3]);
            *(__half2*)&g_Bv[base + D_]     = __floats2half2_rn(v1[0], v1[1]);
            *(__half2*)&g_Bv[base + D_ + 2] = __floats2half2_rn(v1[2], v1[3]);
        }
        #pragma unroll
        for (int off = 16; off > 0; off >>= 1)
            csum += __shfl_xor_sync(0xFFFFFFFFu, csum, off);
        if (lane == 0) g_C[k] = csum;
    } else {
        // zero-init out: 64 blocks x 256 threads x 4 float4 = 1MB
        float4* o4 = (float4*)out;
        const int base = (blk - NB_U - NB_V) * 1024 + tid;
        const float4 z = make_float4(0.f, 0.f, 0.f, 0.f);
        #pragma unroll
        for (int i = 0; i < 4; i++) o4[base + i * 256] = z;
    }
}

// ---------------------------------------------------------------------------
// HMMA GEMM (fp16 single product), split-K=2: out[1024,256] += U*V^T.
// CTA tile 64x32, KC=128 per stage, double-buffered, 2 CTAs/SM.
// Grid (16, 8, 2) = 256 CTAs, all resident.
// ---------------------------------------------------------------------------
#define BM 64
#define BN 32
#define KC 128
#define KSPLIT 2
#define KPER (J_ / KSPLIT)        // 512
#define NSTAGE (KPER / KC)        // 4
#define ROWB 272                  // 128 fp16 (256B) + 16B pad -> conflict-free ldmatrix
#define OFF_A 0
#define OFF_B (BM * ROWB)                     // 17408
#define STAGE_BYTES ((BM + BN) * ROWB)        // 26112

__device__ __forceinline__ void ldm4(uint32_t* f, uint32_t addr) {
    asm volatile("ldmatrix.sync.aligned.m8n8.x4.shared.b16 {%0,%1,%2,%3}, [%4];"
                 : "=r"(f[0]), "=r"(f[1]), "=r"(f[2]), "=r"(f[3]) : "r"(addr));
}
__device__ __forceinline__ void mma16816(float* c, const uint32_t* a, uint32_t b0, uint32_t b1) {
    asm volatile("mma.sync.aligned.m16n8k16.row.col.f32.f16.f16.f32 "
                 "{%0,%1,%2,%3}, {%4,%5,%6,%7}, {%8,%9}, {%0,%1,%2,%3};"
                 : "+f"(c[0]), "+f"(c[1]), "+f"(c[2]), "+f"(c[3])
                 : "r"(a[0]), "r"(a[1]), "r"(a[2]), "r"(a[3]), "r"(b0), "r"(b1));
}

__device__ __forceinline__ void load_stage(uint32_t sb, int m0, int n0, int kelem, int tid) {
    const char* baseA = (const char*)g_A;
    const char* baseB = (const char*)g_Bv;
    const size_t kb = (size_t)kelem * 2;   // byte offset within a 2048B row
    #pragma unroll
    for (int i = 0; i < 4; i++) {          // A: 64 rows x 16 chunks = 1024 positions
        int idx = tid + i * 256;
        int r = idx >> 4, c = idx & 15;
        uint32_t so = (uint32_t)(r * ROWB + c * 16);
        size_t go = (size_t)(m0 + r) * 2048 + kb + c * 16;
        cpasync16(sb + OFF_A + so, baseA + go);
    }
    #pragma unroll
    for (int i = 0; i < 2; i++) {          // B: 32 rows x 16 chunks = 512 positions
        int idx = tid + i * 256;
        int r = idx >> 4, c = idx & 15;
        uint32_t so = (uint32_t)(r * ROWB + c * 16);
        size_t go = (size_t)(n0 + r) * 2048 + kb + c * 16;
        cpasync16(sb + OFF_B + so, baseB + go);
    }
    asm volatile("cp.async.commit_group;\n" ::: "memory");
}

__global__ __launch_bounds__(256, 2) void gemm_kernel(float* __restrict__ out) {
    extern __shared__ char dyn[];
    __shared__ float Cs[BN];

    const int tid = threadIdx.x;
    const int wid = tid >> 5, lane = tid & 31;
    const int m0 = blockIdx.x * BM;
    const int n0 = blockIdx.y * BN;
    const int kbase = blockIdx.z * KPER;
    const int mw = (wid & 3) * 16;         // warp M offset
    const int nw = (wid >> 2) * 16;        // warp N offset

    const uint32_t sbase = smem_u32(dyn);

    load_stage(sbase, m0, n0, kbase, tid);
    if (tid < BN) Cs[tid] = g_C[n0 + tid];

    float acc0[4] = {0.f, 0.f, 0.f, 0.f};  // cols nw..nw+7
    float acc1[4] = {0.f, 0.f, 0.f, 0.f};  // cols nw+8..nw+15

    const uint32_t aRow = (uint32_t)((mw + (lane & 15)) * ROWB);
    const uint32_t aCol = (uint32_t)((lane >> 4) * 16);
    const uint32_t bRow = (uint32_t)((nw + (lane & 7) + ((lane >> 4) << 3)) * ROWB);
    const uint32_t bCol = (uint32_t)((((lane >> 3) & 1) << 3) * 2);

    for (int s = 0; s < NSTAGE; s++) {
        if (s + 1 < NSTAGE) {
            load_stage(sbase + ((s + 1) & 1) * STAGE_BYTES, m0, n0, kbase + (s + 1) * KC, tid);
            asm volatile("cp.async.wait_group 1;\n" ::: "memory");
        } else {
            asm volatile("cp.async.wait_group 0;\n" ::: "memory");
        }
        __syncthreads();

        const uint32_t sb = sbase + (s & 1) * STAGE_BYTES;
        #pragma unroll
        for (int kk = 0; kk < KC / 16; kk++) {
            const uint32_t kb = (uint32_t)(kk * 32);
            uint32_t aF[4], bF[4];
            ldm4(aF, sb + OFF_A + aRow + aCol + kb);
            ldm4(bF, sb + OFF_B + bRow + bCol + kb);
            mma16816(acc0, aF, bF[0], bF[1]);
            mma16816(acc1, aF, bF[2], bF[3]);
        }
        __syncthreads();
    }

    // Epilogue: atomic accumulate (out zero-initialized by prep).
    // Each split contributes 0.5*C so the two splits together add C once.
    const int row = lane >> 2;
    const int col = (lane & 3) * 2;
    const int gr0 = m0 + mw + row;
    const int gc0 = n0 + nw + col;
    const float c00 = 0.5f * Cs[nw + col],     c01 = 0.5f * Cs[nw + col + 1];
    const float c10 = 0.5f * Cs[nw + col + 8], c11 = 0.5f * Cs[nw + col + 9];
    float* o0 = out + (size_t)gr0 * K_ + gc0;
    float* o1 = out + (size_t)(gr0 + 8) * K_ + gc0;
    atomicAdd(o0 + 0, acc0[0] + c00);
    atomicAdd(o0 + 1, acc0[1] + c01);
    atomicAdd(o1 + 0, acc0[2] + c00);
    atomicAdd(o1 + 1, acc0[3] + c01);
    atomicAdd(o0 + 8, acc1[0] + c10);
    atomicAdd(o0 + 9, acc1[1] + c11);
    atomicAdd(o1 + 8, acc1[2] + c10);
    atomicAdd(o1 + 9, acc1[3] + c11);
}

// ---------------------------------------------------------------------------
extern "C" void kernel_launch(void* const* d_in, const int* in_sizes, int n_in,
                              void* d_out, int out_size) {
    const float* x     = (const float*)d_in[0];
    const float* means = (const float*)d_in[1];
    const float* rho   = (const float*)d_in[2];
    float* out = (float*)d_out;

    cudaFuncSetAttribute(gemm_kernel, cudaFuncAttributeMaxDynamicSharedMemorySize,
                         2 * STAGE_BYTES);

    prep_kernel<<<NB_U + NB_V + NB_Z, 256>>>(x, means, rho, out);
    gemm_kernel<<<dim3(B_ / BM, K_ / BN, KSPLIT), 256, 2 * STAGE_BYTES>>>(out);
}

// round 6
// speedup vs baseline: 1.6000x; 1.2149x over previous
#include <cuda_runtime.h>
#include <cuda_fp16.h>
#include <cstdint>
#include <math.h>

#define B_ 1024
#define D_ 512
#define K_ 256
#define J_ 1024   // reduction length: [x^2 | x]

// ---------------- scratch (no allocations allowed) ----------------
__device__ __half g_A[B_ * J_];   // [b][j]: j<512 -> x^2, j>=512 -> x
__device__ __half g_Bv[K_ * J_];  // [k][j]: j<512 -> 0.5*s2, j>=512 -> -m*s2
__device__ float g_C[K_];         // 0.5 * sum_d m^2 s2

__device__ __forceinline__ uint32_t smem_u32(const void* p) {
    uint32_t a;
    asm("{ .reg .u64 t; cvta.to.shared.u64 t, %1; cvt.u32.u64 %0, t; }" : "=r"(a) : "l"(p));
    return a;
}
__device__ __forceinline__ void cpasync16(uint32_t dst, const void* src) {
    asm volatile("cp.async.cg.shared.global [%0], [%1], 16;\n" :: "r"(dst), "l"(src) : "memory");
}
template <int N> __device__ __forceinline__ void cp_wait() {
    asm volatile("cp.async.wait_group %0;\n" :: "n"(N) : "memory");
}

// ---------------------------------------------------------------------------
// Fused prep.
//  blocks [0,256):   U rows from x (fp16), 2 float4 per thread.
//  blocks [256,288): V rows (one warp per k) + warp-shfl C reduction.
//  blocks [288,320): zero-init out (8 float4 per thread).
// ---------------------------------------------------------------------------
#define NB_U 256
#define NB_V 32
#define NB_Z 32

__global__ __launch_bounds__(256) void prep_kernel(const float* __restrict__ x,
                                                   const float* __restrict__ means,
                                                   const float* __restrict__ rho,
                                                   float* __restrict__ out) {
    const int blk = blockIdx.x;
    const int tid = threadIdx.x;
    if (blk < NB_U) {
        #pragma unroll
        for (int i = 0; i < 2; i++) {
            const int idx = blk * 256 + tid + i * 65536;  // float4 index over B*D/4
            const int b = idx >> 7;                       // 128 float4 per x row
            const int d = (idx & 127) * 4;
            float4 xv = ((const float4*)x)[idx];
            size_t base = (size_t)b * J_ + d;
            *(__half2*)&g_A[base]          = __floats2half2_rn(xv.x * xv.x, xv.y * xv.y);
            *(__half2*)&g_A[base + 2]      = __floats2half2_rn(xv.z * xv.z, xv.w * xv.w);
            *(__half2*)&g_A[base + D_]     = __floats2half2_rn(xv.x, xv.y);
            *(__half2*)&g_A[base + D_ + 2] = __floats2half2_rn(xv.z, xv.w);
        }
    } else if (blk < NB_U + NB_V) {
        const int wid = tid >> 5, lane = tid & 31;
        const int k = (blk - NB_U) * 8 + wid;      // 32 blocks x 8 warps = 256 k's
        const float4* mrow = (const float4*)(means + (size_t)k * D_);
        const float4* rrow = (const float4*)(rho   + (size_t)k * D_);
        float csum = 0.0f;
        #pragma unroll
        for (int i = 0; i < 4; i++) {
            int d4 = lane + i * 32;                // float4 index 0..127
            float4 m = mrow[d4];
            float4 r = rrow[d4];
            float mm[4] = {m.x, m.y, m.z, m.w};
            float rr[4] = {r.x, r.y, r.z, r.w};
            float v0[4], v1[4];
            #pragma unroll
            for (int c = 0; c < 4; c++) {
                float s  = __logf(1.0f + __expf(rr[c]));   // softplus (fast)
                float s2 = s * s;
                v0[c] = 0.5f * s2;
                v1[c] = -mm[c] * s2;
                csum += 0.5f * mm[c] * mm[c] * s2;
            }
            size_t base = (size_t)k * J_ + d4 * 4;
            *(__half2*)&g_Bv[base]          = __floats2half2_rn(v0[0], v0[1]);
            *(__half2*)&g_Bv[base + 2]      = __floats2half2_rn(v0[2], v0[3]);
            *(__half2*)&g_Bv[base + D_]     = __floats2half2_rn(v1[0], v1[1]);
            *(__half2*)&g_Bv[base + D_ + 2] = __floats2half2_rn(v1[2], v1[3]);
        }
        #pragma unroll
        for (int off = 16; off > 0; off >>= 1)
            csum += __shfl_xor_sync(0xFFFFFFFFu, csum, off);
        if (lane == 0) g_C[k] = csum;
    } else {
        float4* o4 = (float4*)out;
        const int base = (blk - NB_U - NB_V) * 256 + tid;   // 8192 per pass
        const float4 z = make_float4(0.f, 0.f, 0.f, 0.f);
        #pragma unroll
        for (int i = 0; i < 8; i++) o4[base + i * 8192] = z;
    }
}

// ---------------------------------------------------------------------------
// HMMA GEMM (fp16), split-K=4: out[1024,256] += U*V^T (+ C from z==0 only).
// CTA tile 64x64, KC=64, ring-of-4 fully preloaded (CTA loads its entire
// 64KB working set in the prologue at max MLP). Grid (16,4,4)=256 CTAs,
// 2 CTAs/SM resident (147KB smem/SM).
// 8 warps = 4(M) x 2(N); warp tile 16x32 -> 4 independent acc chains.
// ---------------------------------------------------------------------------
#define BM 64
#define BN 64
#define KC 64
#define KSPLIT 4
#define KPER (J_ / KSPLIT)        // 256
#define NSTAGE (KPER / KC)        // 4
#define ROWB 144                  // 64 fp16 (128B) + 16B pad -> conflict-free
#define OFF_A 0
#define OFF_B (BM * ROWB)                     // 9216
#define STAGE_BYTES ((BM + BN) * ROWB)        // 18432

__device__ __forceinline__ void ldm4(uint32_t* f, uint32_t addr) {
    asm volatile("ldmatrix.sync.aligned.m8n8.x4.shared.b16 {%0,%1,%2,%3}, [%4];"
                 : "=r"(f[0]), "=r"(f[1]), "=r"(f[2]), "=r"(f[3]) : "r"(addr));
}
__device__ __forceinline__ void mma16816(float* c, const uint32_t* a, uint32_t b0, uint32_t b1) {
    asm volatile("mma.sync.aligned.m16n8k16.row.col.f32.f16.f16.f32 "
                 "{%0,%1,%2,%3}, {%4,%5,%6,%7}, {%8,%9}, {%0,%1,%2,%3};"
                 : "+f"(c[0]), "+f"(c[1]), "+f"(c[2]), "+f"(c[3])
                 : "r"(a[0]), "r"(a[1]), "r"(a[2]), "r"(a[3]), "r"(b0), "r"(b1));
}

__device__ __forceinline__ void load_stage(uint32_t sb, int m0, int n0, int kelem, int tid) {
    const char* baseA = (const char*)g_A;
    const char* baseB = (const char*)g_Bv;
    const size_t kb = (size_t)kelem * 2;   // byte offset within a 2048B row
    #pragma unroll
    for (int i = 0; i < 2; i++) {          // A: 64 rows x 8 chunks = 512 positions
        int idx = tid + i * 256;
        int r = idx >> 3, c = idx & 7;
        uint32_t so = (uint32_t)(r * ROWB + c * 16);
        cpasync16(sb + OFF_A + so, baseA + (size_t)(m0 + r) * 2048 + kb + c * 16);
    }
    #pragma unroll
    for (int i = 0; i < 2; i++) {          // B: 64 rows x 8 chunks = 512 positions
        int idx = tid + i * 256;
        int r = idx >> 3, c = idx & 7;
        uint32_t so = (uint32_t)(r * ROWB + c * 16);
        cpasync16(sb + OFF_B + so, baseB + (size_t)(n0 + r) * 2048 + kb + c * 16);
    }
    asm volatile("cp.async.commit_group;\n" ::: "memory");
}

__global__ __launch_bounds__(256, 2) void gemm_kernel(float* __restrict__ out) {
    extern __shared__ char dyn[];
    __shared__ float Cs[BN];

    const int tid = threadIdx.x;
    const int wid = tid >> 5, lane = tid & 31;
    const int m0 = blockIdx.x * BM;
    const int n0 = blockIdx.y * BN;
    const int kbase = blockIdx.z * KPER;
    const int mw = (wid & 3) * 16;         // warp M offset
    const int nw = (wid >> 2) * 32;        // warp N offset

    const uint32_t sbase = smem_u32(dyn);

    // Prologue: issue ALL stages' loads at once (max MLP, one L2 latency).
    #pragma unroll
    for (int s = 0; s < NSTAGE; s++)
        load_stage(sbase + s * STAGE_BYTES, m0, n0, kbase + s * KC, tid);

    if (tid < BN) Cs[tid] = g_C[n0 + tid];

    float acc[16];
    #pragma unroll
    for (int i = 0; i < 16; i++) acc[i] = 0.f;

    const uint32_t aRow  = (uint32_t)((mw + (lane & 15)) * ROWB);
    const uint32_t aCol  = (uint32_t)((lane >> 4) * 16);
    const uint32_t bRow0 = (uint32_t)((nw + (lane & 7) + ((lane >> 4) << 3)) * ROWB);
    const uint32_t bRow1 = bRow0 + 16 * ROWB;
    const uint32_t bCol  = (uint32_t)((((lane >> 3) & 1) << 3) * 2);

    #pragma unroll
    for (int s = 0; s < NSTAGE; s++) {
        if (s == 0)      cp_wait<3>();
        else if (s == 1) cp_wait<2>();
        else if (s == 2) cp_wait<1>();
        else             cp_wait<0>();
        __syncthreads();

        const uint32_t sb = sbase + s * STAGE_BYTES;
        #pragma unroll
        for (int kk = 0; kk < KC / 16; kk++) {
            const uint32_t kbb = (uint32_t)(kk * 32);
            uint32_t aF[4], b0[4], b1[4];
            ldm4(aF, sb + OFF_A + aRow + aCol + kbb);
            ldm4(b0, sb + OFF_B + bRow0 + bCol + kbb);
            ldm4(b1, sb + OFF_B + bRow1 + bCol + kbb);
            mma16816(acc + 0,  aF, b0[0], b0[1]);
            mma16816(acc + 4,  aF, b0[2], b0[3]);
            mma16816(acc + 8,  aF, b1[0], b1[1]);
            mma16816(acc + 12, aF, b1[2], b1[3]);
        }
        // no trailing barrier: buffers are never reused
    }

    // Epilogue: atomic accumulate (out zero-initialized by prep).
    // Only the z==0 split adds the bias C.
    const int row = lane >> 2;
    const int col = (lane & 3) * 2;
    const int gr0 = m0 + mw + row;
    const bool addc = (blockIdx.z == 0);
    #pragma unroll
    for (int j = 0; j < 4; j++) {
        const int gc = n0 + nw + j * 8 + col;
        const float cA = addc ? Cs[nw + j * 8 + col]     : 0.f;
        const float cB = addc ? Cs[nw + j * 8 + col + 1] : 0.f;
        float* oT = out + (size_t)gr0 * K_ + gc;
        float* oB = out + (size_t)(gr0 + 8) * K_ + gc;
        atomicAdd(oT + 0, acc[j * 4 + 0] + cA);
        atomicAdd(oT + 1, acc[j * 4 + 1] + cB);
        atomicAdd(oB + 0, acc[j * 4 + 2] + cA);
        atomicAdd(oB + 1, acc[j * 4 + 3] + cB);
    }
}

// ---------------------------------------------------------------------------
extern "C" void kernel_launch(void* const* d_in, const int* in_sizes, int n_in,
                              void* d_out, int out_size) {
    const float* x     = (const float*)d_in[0];
    const float* means = (const float*)d_in[1];
    const float* rho   = (const float*)d_in[2];
    float* out = (float*)d_out;

    cudaFuncSetAttribute(gemm_kernel, cudaFuncAttributeMaxDynamicSharedMemorySize,
                         NSTAGE * STAGE_BYTES);

    prep_kernel<<<NB_U + NB_V + NB_Z, 256>>>(x, means, rho, out);
    gemm_kernel<<<dim3(B_ / BM, K_ / BN, KSPLIT), 256, NSTAGE * STAGE_BYTES>>>(out);
}